// round 1
// baseline (speedup 1.0000x reference)
#include <cuda_runtime.h>

// Problem dims
#define BATCH   128
#define TSTEPS  32
#define D_DIM   6400
#define HID     1000
#define ACT     4
#define M_DIM   (BATCH * TSTEPS)   // 4096
#define N_DIM   HID                // 1000
#define K_DIM   D_DIM              // 6400

#define BETA_F  0.99f
#define THR_F   1.0f

// Scratch: H1[m, n] = x[m, :] . W1[n, :] + b1[n]   (16.384 MB)
__device__ float g_H1[M_DIM * N_DIM];

// ---------------------------------------------------------------------------
// Kernel 1: fp32 SGEMM (NT: both operands K-contiguous)
//   C[m,n] = sum_k A[m,k] * B[n,k] + bias[n]
// BM=128, BN=128, BK=16, 256 threads, 8x8 per-thread micro-tile
// ---------------------------------------------------------------------------
__global__ __launch_bounds__(256, 2)
void gemm_h1_kernel(const float* __restrict__ A,
                    const float* __restrict__ Bm,
                    const float* __restrict__ bias)
{
    const int BM = 128, BN = 128, BK = 16;
    __shared__ float As[BK][BM + 4];
    __shared__ float Bs[BK][BN + 4];

    const int bn  = blockIdx.x * BN;
    const int bm  = blockIdx.y * BM;
    const int tid = threadIdx.x;

    const int tx = tid & 15;       // 0..15  -> n micro-tile
    const int ty = tid >> 4;       // 0..15  -> m micro-tile

    // load mapping: 256 threads, each loads 2x float4 from A and B tiles
    const int lrow = tid >> 2;           // 0..63
    const int lcol = (tid & 3) * 4;      // 0,4,8,12

    float acc[8][8];
#pragma unroll
    for (int i = 0; i < 8; i++)
#pragma unroll
        for (int j = 0; j < 8; j++) acc[i][j] = 0.0f;

    const int n0 = bn + lrow;
    const int n1 = bn + lrow + 64;

    for (int k0 = 0; k0 < K_DIM; k0 += BK) {
        // ---- global loads into registers ----
        float4 a0 = *(const float4*)(A + (size_t)(bm + lrow)      * K_DIM + k0 + lcol);
        float4 a1 = *(const float4*)(A + (size_t)(bm + lrow + 64) * K_DIM + k0 + lcol);
        float4 b0 = make_float4(0.f, 0.f, 0.f, 0.f);
        float4 b1 = make_float4(0.f, 0.f, 0.f, 0.f);
        if (n0 < N_DIM) b0 = *(const float4*)(Bm + (size_t)n0 * K_DIM + k0 + lcol);
        if (n1 < N_DIM) b1 = *(const float4*)(Bm + (size_t)n1 * K_DIM + k0 + lcol);

        __syncthreads();   // previous iteration done reading smem

        // ---- store transposed into smem ----
        As[lcol + 0][lrow] = a0.x;  As[lcol + 1][lrow] = a0.y;
        As[lcol + 2][lrow] = a0.z;  As[lcol + 3][lrow] = a0.w;
        As[lcol + 0][lrow + 64] = a1.x;  As[lcol + 1][lrow + 64] = a1.y;
        As[lcol + 2][lrow + 64] = a1.z;  As[lcol + 3][lrow + 64] = a1.w;

        Bs[lcol + 0][lrow] = b0.x;  Bs[lcol + 1][lrow] = b0.y;
        Bs[lcol + 2][lrow] = b0.z;  Bs[lcol + 3][lrow] = b0.w;
        Bs[lcol + 0][lrow + 64] = b1.x;  Bs[lcol + 1][lrow + 64] = b1.y;
        Bs[lcol + 2][lrow + 64] = b1.z;  Bs[lcol + 3][lrow + 64] = b1.w;

        __syncthreads();

        // ---- compute ----
#pragma unroll
        for (int kk = 0; kk < BK; kk++) {
            float ar[8], br[8];
            const float4* pa = (const float4*)&As[kk][ty * 8];
            const float4* pb = (const float4*)&Bs[kk][tx * 8];
            float4 av0 = pa[0], av1 = pa[1];
            float4 bv0 = pb[0], bv1 = pb[1];
            ar[0]=av0.x; ar[1]=av0.y; ar[2]=av0.z; ar[3]=av0.w;
            ar[4]=av1.x; ar[5]=av1.y; ar[6]=av1.z; ar[7]=av1.w;
            br[0]=bv0.x; br[1]=bv0.y; br[2]=bv0.z; br[3]=bv0.w;
            br[4]=bv1.x; br[5]=bv1.y; br[6]=bv1.z; br[7]=bv1.w;
#pragma unroll
            for (int i = 0; i < 8; i++)
#pragma unroll
                for (int j = 0; j < 8; j++)
                    acc[i][j] = fmaf(ar[i], br[j], acc[i][j]);
        }
    }

    // ---- epilogue: add bias, store ----
#pragma unroll
    for (int i = 0; i < 8; i++) {
        const int m = bm + ty * 8 + i;
#pragma unroll
        for (int j = 0; j < 8; j++) {
            const int n = bn + tx * 8 + j;
            if (n < N_DIM)
                g_H1[(size_t)m * N_DIM + n] = acc[i][j] + bias[n];
        }
    }
}

// ---------------------------------------------------------------------------
// Kernel 2: temporal LIF recurrence.
// One block per batch element b. mem1[1000] lives in registers (4 per thread),
// W2 [4,1000] cached in smem, mem2[4] owned by thread 0.
// snntorch Leaky, reset_mechanism='zero':
//   reset   = (mem_prev > thr)
//   mem_new = reset ? 0 : beta*mem_prev + cur
//   spk     = (mem_new > thr)
// ---------------------------------------------------------------------------
__global__ __launch_bounds__(256)
void snn_recurrence_kernel(const float* __restrict__ W2,
                           const float* __restrict__ b2,
                           float* __restrict__ out)
{
    __shared__ float sW2[ACT][HID];
    __shared__ float sred[8][ACT];

    const int b   = blockIdx.x;
    const int tid = threadIdx.x;
    const int lane = tid & 31;
    const int warp = tid >> 5;

    for (int i = tid; i < ACT * HID; i += 256)
        sW2[i / HID][i % HID] = W2[i];
    __syncthreads();

    float m1[4] = {0.f, 0.f, 0.f, 0.f};
    float m2[ACT] = {0.f, 0.f, 0.f, 0.f};   // meaningful on thread 0 only

    for (int t = 0; t < TSTEPS; t++) {
        float acc0 = 0.f, acc1 = 0.f, acc2 = 0.f, acc3 = 0.f;
        const float* h1row = g_H1 + ((size_t)(b * TSTEPS + t)) * HID;

#pragma unroll
        for (int j = 0; j < 4; j++) {
            const int h = tid + j * 256;
            if (h < HID) {
                const float cur = h1row[h];
                const float mn  = (m1[j] > THR_F) ? 0.0f : fmaf(BETA_F, m1[j], cur);
                m1[j] = mn;
                const float spk = (mn > THR_F) ? 1.0f : 0.0f;
                acc0 = fmaf(spk, sW2[0][h], acc0);
                acc1 = fmaf(spk, sW2[1][h], acc1);
                acc2 = fmaf(spk, sW2[2][h], acc2);
                acc3 = fmaf(spk, sW2[3][h], acc3);
            }
        }

        // warp reduce
#pragma unroll
        for (int o = 16; o; o >>= 1) {
            acc0 += __shfl_xor_sync(0xffffffffu, acc0, o);
            acc1 += __shfl_xor_sync(0xffffffffu, acc1, o);
            acc2 += __shfl_xor_sync(0xffffffffu, acc2, o);
            acc3 += __shfl_xor_sync(0xffffffffu, acc3, o);
        }
        if (lane == 0) {
            sred[warp][0] = acc0; sred[warp][1] = acc1;
            sred[warp][2] = acc2; sred[warp][3] = acc3;
        }
        __syncthreads();

        if (tid == 0) {
#pragma unroll
            for (int a = 0; a < ACT; a++) {
                float h2 = b2[a];
#pragma unroll
                for (int w = 0; w < 8; w++) h2 += sred[w][a];
                const float mn = (m2[a] > THR_F) ? 0.0f : fmaf(BETA_F, m2[a], h2);
                m2[a] = mn;
                out[((size_t)b * TSTEPS + t) * ACT + a] = (mn > THR_F) ? 1.0f : 0.0f;
            }
        }
        __syncthreads();   // sred reuse next step
    }
}

// ---------------------------------------------------------------------------
extern "C" void kernel_launch(void* const* d_in, const int* in_sizes, int n_in,
                              void* d_out, int out_size)
{
    const float* x  = (const float*)d_in[0];   // [128,32,6400]
    const float* W1 = (const float*)d_in[1];   // [1000,6400]
    const float* b1 = (const float*)d_in[2];   // [1000]
    const float* W2 = (const float*)d_in[3];   // [4,1000]
    const float* b2 = (const float*)d_in[4];   // [4]
    float* out = (float*)d_out;                // [128,32,4]

    dim3 grid((N_DIM + 127) / 128, M_DIM / 128);   // (8, 32)
    gemm_h1_kernel<<<grid, 256>>>(x, W1, b1);
    snn_recurrence_kernel<<<BATCH, 256>>>(W2, b2, out);
}

// round 2
// speedup vs baseline: 1.0020x; 1.0020x over previous
#include <cuda_runtime.h>

// Problem dims
#define BATCH   128
#define TSTEPS  32
#define D_DIM   6400
#define HID     1000
#define ACT     4
#define M_DIM   (BATCH * TSTEPS)   // 4096
#define N_DIM   HID                // 1000
#define K_DIM   D_DIM              // 6400

#define BETA_F  0.99f
#define THR_F   1.0f

// Scratch: H1[m, n] = x[m, :] . W1[n, :] + b1[n]   (16.384 MB)
__device__ float g_H1[M_DIM * N_DIM];

// ---------------------------------------------------------------------------
// Kernel 1: fp32 SGEMM (NT: both operands K-contiguous)
//   C[m,n] = sum_k A[m,k] * B[n,k] + bias[n]
// BM=128, BN=128, BK=16, 256 threads, 8x8 per-thread micro-tile
// ---------------------------------------------------------------------------
__global__ __launch_bounds__(256, 2)
void gemm_h1_kernel(const float* __restrict__ A,
                    const float* __restrict__ Bm,
                    const float* __restrict__ bias)
{
    const int BM = 128, BN = 128, BK = 16;
    __shared__ float As[BK][BM + 4];
    __shared__ float Bs[BK][BN + 4];

    const int bn  = blockIdx.x * BN;
    const int bm  = blockIdx.y * BM;
    const int tid = threadIdx.x;

    const int tx = tid & 15;       // 0..15  -> n micro-tile
    const int ty = tid >> 4;       // 0..15  -> m micro-tile

    // load mapping: 256 threads, each loads 2x float4 from A and B tiles
    const int lrow = tid >> 2;           // 0..63
    const int lcol = (tid & 3) * 4;      // 0,4,8,12

    float acc[8][8];
#pragma unroll
    for (int i = 0; i < 8; i++)
#pragma unroll
        for (int j = 0; j < 8; j++) acc[i][j] = 0.0f;

    const int n0 = bn + lrow;
    const int n1 = bn + lrow + 64;

    for (int k0 = 0; k0 < K_DIM; k0 += BK) {
        // ---- global loads into registers ----
        float4 a0 = *(const float4*)(A + (size_t)(bm + lrow)      * K_DIM + k0 + lcol);
        float4 a1 = *(const float4*)(A + (size_t)(bm + lrow + 64) * K_DIM + k0 + lcol);
        float4 b0 = make_float4(0.f, 0.f, 0.f, 0.f);
        float4 b1 = make_float4(0.f, 0.f, 0.f, 0.f);
        if (n0 < N_DIM) b0 = *(const float4*)(Bm + (size_t)n0 * K_DIM + k0 + lcol);
        if (n1 < N_DIM) b1 = *(const float4*)(Bm + (size_t)n1 * K_DIM + k0 + lcol);

        __syncthreads();   // previous iteration done reading smem

        // ---- store transposed into smem ----
        As[lcol + 0][lrow] = a0.x;  As[lcol + 1][lrow] = a0.y;
        As[lcol + 2][lrow] = a0.z;  As[lcol + 3][lrow] = a0.w;
        As[lcol + 0][lrow + 64] = a1.x;  As[lcol + 1][lrow + 64] = a1.y;
        As[lcol + 2][lrow + 64] = a1.z;  As[lcol + 3][lrow + 64] = a1.w;

        Bs[lcol + 0][lrow] = b0.x;  Bs[lcol + 1][lrow] = b0.y;
        Bs[lcol + 2][lrow] = b0.z;  Bs[lcol + 3][lrow] = b0.w;
        Bs[lcol + 0][lrow + 64] = b1.x;  Bs[lcol + 1][lrow + 64] = b1.y;
        Bs[lcol + 2][lrow + 64] = b1.z;  Bs[lcol + 3][lrow + 64] = b1.w;

        __syncthreads();

        // ---- compute ----
#pragma unroll
        for (int kk = 0; kk < BK; kk++) {
            float ar[8], br[8];
            const float4* pa = (const float4*)&As[kk][ty * 8];
            const float4* pb = (const float4*)&Bs[kk][tx * 8];
            float4 av0 = pa[0], av1 = pa[1];
            float4 bv0 = pb[0], bv1 = pb[1];
            ar[0]=av0.x; ar[1]=av0.y; ar[2]=av0.z; ar[3]=av0.w;
            ar[4]=av1.x; ar[5]=av1.y; ar[6]=av1.z; ar[7]=av1.w;
            br[0]=bv0.x; br[1]=bv0.y; br[2]=bv0.z; br[3]=bv0.w;
            br[4]=bv1.x; br[5]=bv1.y; br[6]=bv1.z; br[7]=bv1.w;
#pragma unroll
            for (int i = 0; i < 8; i++)
#pragma unroll
                for (int j = 0; j < 8; j++)
                    acc[i][j] = fmaf(ar[i], br[j], acc[i][j]);
        }
    }

    // ---- epilogue: add bias, store ----
#pragma unroll
    for (int i = 0; i < 8; i++) {
        const int m = bm + ty * 8 + i;
#pragma unroll
        for (int j = 0; j < 8; j++) {
            const int n = bn + tx * 8 + j;
            if (n < N_DIM)
                g_H1[(size_t)m * N_DIM + n] = acc[i][j] + bias[n];
        }
    }
}

// ---------------------------------------------------------------------------
// Kernel 2: temporal LIF recurrence.
// One block per batch element b. mem1[1000] lives in registers (4 per thread),
// W2 [4,1000] cached in smem, mem2[4] owned by thread 0.
// snntorch Leaky, reset_mechanism='zero':
//   reset   = (mem_prev > thr)
//   mem_new = reset ? 0 : beta*mem_prev + cur
//   spk     = (mem_new > thr)
// ---------------------------------------------------------------------------
__global__ __launch_bounds__(256)
void snn_recurrence_kernel(const float* __restrict__ W2,
                           const float* __restrict__ b2,
                           float* __restrict__ out)
{
    __shared__ float sW2[ACT][HID];
    __shared__ float sred[8][ACT];

    const int b   = blockIdx.x;
    const int tid = threadIdx.x;
    const int lane = tid & 31;
    const int warp = tid >> 5;

    for (int i = tid; i < ACT * HID; i += 256)
        sW2[i / HID][i % HID] = W2[i];
    __syncthreads();

    float m1[4] = {0.f, 0.f, 0.f, 0.f};
    float m2[ACT] = {0.f, 0.f, 0.f, 0.f};   // meaningful on thread 0 only

    for (int t = 0; t < TSTEPS; t++) {
        float acc0 = 0.f, acc1 = 0.f, acc2 = 0.f, acc3 = 0.f;
        const float* h1row = g_H1 + ((size_t)(b * TSTEPS + t)) * HID;

#pragma unroll
        for (int j = 0; j < 4; j++) {
            const int h = tid + j * 256;
            if (h < HID) {
                const float cur = h1row[h];
                const float mn  = (m1[j] > THR_F) ? 0.0f : fmaf(BETA_F, m1[j], cur);
                m1[j] = mn;
                const float spk = (mn > THR_F) ? 1.0f : 0.0f;
                acc0 = fmaf(spk, sW2[0][h], acc0);
                acc1 = fmaf(spk, sW2[1][h], acc1);
                acc2 = fmaf(spk, sW2[2][h], acc2);
                acc3 = fmaf(spk, sW2[3][h], acc3);
            }
        }

        // warp reduce
#pragma unroll
        for (int o = 16; o; o >>= 1) {
            acc0 += __shfl_xor_sync(0xffffffffu, acc0, o);
            acc1 += __shfl_xor_sync(0xffffffffu, acc1, o);
            acc2 += __shfl_xor_sync(0xffffffffu, acc2, o);
            acc3 += __shfl_xor_sync(0xffffffffu, acc3, o);
        }
        if (lane == 0) {
            sred[warp][0] = acc0; sred[warp][1] = acc1;
            sred[warp][2] = acc2; sred[warp][3] = acc3;
        }
        __syncthreads();

        if (tid == 0) {
#pragma unroll
            for (int a = 0; a < ACT; a++) {
                float h2 = b2[a];
#pragma unroll
                for (int w = 0; w < 8; w++) h2 += sred[w][a];
                const float mn = (m2[a] > THR_F) ? 0.0f : fmaf(BETA_F, m2[a], h2);
                m2[a] = mn;
                out[((size_t)b * TSTEPS + t) * ACT + a] = (mn > THR_F) ? 1.0f : 0.0f;
            }
        }
        __syncthreads();   // sred reuse next step
    }
}

// ---------------------------------------------------------------------------
extern "C" void kernel_launch(void* const* d_in, const int* in_sizes, int n_in,
                              void* d_out, int out_size)
{
    const float* x  = (const float*)d_in[0];   // [128,32,6400]
    const float* W1 = (const float*)d_in[1];   // [1000,6400]
    const float* b1 = (const float*)d_in[2];   // [1000]
    const float* W2 = (const float*)d_in[3];   // [4,1000]
    const float* b2 = (const float*)d_in[4];   // [4]
    float* out = (float*)d_out;                // [128,32,4]

    dim3 grid((N_DIM + 127) / 128, M_DIM / 128);   // (8, 32)
    gemm_h1_kernel<<<grid, 256>>>(x, W1, b1);
    snn_recurrence_kernel<<<BATCH, 256>>>(W2, b2, out);
}